// round 5
// baseline (speedup 1.0000x reference)
#include <cuda_runtime.h>
#include <cuda_bf16.h>
#include <math.h>
#include <stdint.h>

// ---------------- problem constants ----------------
#define E_        8
#define NTOK      8192
#define D_        1024
#define F_        2816
#define NSLOT     (NTOK * 2)
#define SLOT_PAD  (NSLOT + E_ * 128)   // 17408
#define OUT_ELEMS (NTOK * D_)

// mma GEMM tiling: CTA 128 x (64f|128d), K-stage = 16 bf16, 2-stage double buffer
#define BK        16
#define ROWB      48                    // 32B data + 16B pad per row
#define TILE_B    (128 * ROWB)
#define OFF_AHI   0
#define OFF_ALO   (1 * TILE_B)
#define OFF_BHI   (2 * TILE_B)
#define OFF_BLO   (3 * TILE_B)
#define STAGE_B   (4 * TILE_B)          // 24576; x2 = 48KB static

// probe region sizes
#define PROBE_ACT (128 * F_)            // 360448 bf16
#define PROBE_Y2  (128 * D_)            // 131072 f32

// ---------------- static device scratch ----------------
__device__ __align__(128) __nv_bfloat16 g_xp_hi[(size_t)SLOT_PAD * D_];
__device__ __align__(128) __nv_bfloat16 g_xp_lo[(size_t)SLOT_PAD * D_];
__device__ __align__(128) __nv_bfloat16 g_gt_hi[(size_t)E_ * F_ * D_];
__device__ __align__(128) __nv_bfloat16 g_gt_lo[(size_t)E_ * F_ * D_];
__device__ __align__(128) __nv_bfloat16 g_ut_hi[(size_t)E_ * F_ * D_];
__device__ __align__(128) __nv_bfloat16 g_ut_lo[(size_t)E_ * F_ * D_];
__device__ __align__(128) __nv_bfloat16 g_dt_hi[(size_t)E_ * D_ * F_];
__device__ __align__(128) __nv_bfloat16 g_dt_lo[(size_t)E_ * D_ * F_];
__device__ __align__(128) __nv_bfloat16 g_act_hi[(size_t)SLOT_PAD * F_];
__device__ __align__(128) __nv_bfloat16 g_act_lo[(size_t)SLOT_PAD * F_];
__device__ __align__(128) float         g_y2[(size_t)SLOT_PAD * D_];

__device__ int   g_perm_token[SLOT_PAD];
__device__ float g_perm_w[SLOT_PAD];
__device__ int   g_tok_slot[NSLOT];
__device__ int   g_counts[E_];
__device__ int   g_cursor[E_];
__device__ int   g_pad_off[E_ + 1];
__device__ int   g_topk_idx[NSLOT];
__device__ float g_topk_w[NSLOT];
__device__ int   g_flagA;
__device__ int   g_flagB;

// ---------------- helpers ----------------
static __device__ __forceinline__ uint32_t smem_u32(const void* p) {
    uint32_t a;
    asm("{ .reg .u64 t; cvta.to.shared.u64 t, %1; cvt.u32.u64 %0, t; }" : "=r"(a) : "l"(p));
    return a;
}
static __device__ __forceinline__ void cp16(uint32_t dst, const __nv_bfloat16* src) {
    asm volatile("cp.async.cg.shared.global [%0], [%1], 16;"
                 :: "r"(dst), "l"(__cvta_generic_to_global(src)) : "memory");
}
static __device__ __forceinline__ void cp_commit() {
    asm volatile("cp.async.commit_group;" ::: "memory");
}
template <int N>
static __device__ __forceinline__ void cp_wait() {
    asm volatile("cp.async.wait_group %0;" :: "n"(N) : "memory");
}
static __device__ __forceinline__ void ldsm4(uint32_t* r, uint32_t addr) {
    asm volatile("ldmatrix.sync.aligned.m8n8.x4.shared.b16 {%0,%1,%2,%3}, [%4];"
                 : "=r"(r[0]), "=r"(r[1]), "=r"(r[2]), "=r"(r[3]) : "r"(addr));
}
static __device__ __forceinline__ void mma_bf16(float* d, const uint32_t* a, const uint32_t* b) {
    asm volatile("mma.sync.aligned.m16n8k16.row.col.f32.bf16.bf16.f32 "
                 "{%0,%1,%2,%3}, {%4,%5,%6,%7}, {%8,%9}, {%0,%1,%2,%3};"
                 : "+f"(d[0]), "+f"(d[1]), "+f"(d[2]), "+f"(d[3])
                 : "r"(a[0]), "r"(a[1]), "r"(a[2]), "r"(a[3]), "r"(b[0]), "r"(b[1]));
}
static __device__ __forceinline__ uint32_t toff(int r, int c16) {
    return (uint32_t)(r * ROWB + c16 * 16);
}

// ---------------- init ----------------
__global__ void init_kernel() {
    int i = blockIdx.x * 256 + threadIdx.x;
    if (i < SLOT_PAD) { g_perm_token[i] = -1; g_perm_w[i] = 0.0f; }
    if (i < E_) g_counts[i] = 0;
    if (i == 0) { g_flagA = 0; g_flagB = 0; }
    // zero probe regions so flags are recomputed honestly every call
    if (i < PROBE_ACT) g_act_hi[i] = __float2bfloat16(0.0f);
    if (i < PROBE_Y2)  g_y2[i] = 0.0f;
}

// ---------------- router / scan / fill (R1-proven) ----------------
__global__ void router_kernel(const float* __restrict__ x, const float* __restrict__ rw) {
    int t = blockIdx.x;
    const float* xr = x + (size_t)t * D_;
    int lane = threadIdx.x & 31;
    int w    = threadIdx.x >> 5;

    double s = 0.0;
    for (int d = lane; d < D_; d += 32)
        s += (double)xr[d] * (double)rw[d * E_ + w];
    #pragma unroll
    for (int o = 16; o > 0; o >>= 1)
        s += __shfl_down_sync(0xffffffffu, s, o);

    __shared__ double sc[E_];
    if (lane == 0) sc[w] = s;
    __syncthreads();

    if (threadIdx.x == 0) {
        double m = sc[0];
        #pragma unroll
        for (int e = 1; e < E_; e++) m = fmax(m, sc[e]);
        double p[E_], sum = 0.0;
        #pragma unroll
        for (int e = 0; e < E_; e++) { p[e] = exp(sc[e] - m); sum += p[e]; }
        #pragma unroll
        for (int e = 0; e < E_; e++) p[e] /= sum;
        int i0 = 0;
        #pragma unroll
        for (int e = 1; e < E_; e++) if (p[e] > p[i0]) i0 = e;
        int i1 = (i0 == 0) ? 1 : 0;
        #pragma unroll
        for (int e = 0; e < E_; e++) { if (e == i0) continue; if (p[e] > p[i1]) i1 = e; }
        float p0 = (float)p[i0], p1 = (float)p[i1];
        float inv = 1.0f / (p0 + p1);
        g_topk_idx[t * 2 + 0] = i0;  g_topk_idx[t * 2 + 1] = i1;
        g_topk_w[t * 2 + 0] = p0 * inv;  g_topk_w[t * 2 + 1] = p1 * inv;
        atomicAdd(&g_counts[i0], 1);
        atomicAdd(&g_counts[i1], 1);
    }
}

__global__ void scan_kernel() {
    int off = 0;
    #pragma unroll
    for (int e = 0; e < E_; e++) {
        g_pad_off[e] = off;  g_cursor[e] = off;
        off += (g_counts[e] + 127) & ~127;
    }
    g_pad_off[E_] = off;
}

__global__ void fill_kernel() {
    int idx = blockIdx.x * blockDim.x + threadIdx.x;
    if (idx >= NSLOT) return;
    int e    = g_topk_idx[idx];
    int slot = atomicAdd(&g_cursor[e], 1);
    g_perm_token[slot] = idx >> 1;
    g_perm_w[slot]     = g_topk_w[idx];
    g_tok_slot[idx]    = slot;
}

__global__ void xgather_kernel(const float* __restrict__ x) {
    int slot = blockIdx.x;
    int tok  = g_perm_token[slot];
    size_t base = (size_t)slot * D_;
    for (int d = threadIdx.x; d < D_; d += blockDim.x) {
        float v = (tok >= 0) ? x[(size_t)tok * D_ + d] : 0.0f;
        __nv_bfloat16 h = __float2bfloat16(v);
        g_xp_hi[base + d] = h;
        g_xp_lo[base + d] = __float2bfloat16(v - __bfloat162float(h));
    }
}

__global__ void tconv_kernel(const float* __restrict__ in,
                             __nv_bfloat16* __restrict__ oh,
                             __nv_bfloat16* __restrict__ ol,
                             int R, int C) {
    __shared__ float t[32][33];
    int e  = blockIdx.z;
    int c0 = blockIdx.x * 32, r0 = blockIdx.y * 32;
    const float* src = in + (size_t)e * R * C;
    #pragma unroll
    for (int i = 0; i < 4; i++) {
        int r = r0 + threadIdx.y + i * 8;
        t[threadIdx.y + i * 8][threadIdx.x] = src[(size_t)r * C + c0 + threadIdx.x];
    }
    __syncthreads();
    #pragma unroll
    for (int i = 0; i < 4; i++) {
        int c = c0 + threadIdx.y + i * 8;
        float v = t[threadIdx.x][threadIdx.y + i * 8];
        __nv_bfloat16 h = __float2bfloat16(v);
        size_t o = (size_t)e * R * C + (size_t)c * R + r0 + threadIdx.x;
        oh[o] = h;
        ol[o] = __float2bfloat16(v - __bfloat162float(h));
    }
}

// ---------------- mma stage loaders ----------------
static __device__ __forceinline__ void g1_load(uint32_t stb, int row0, int e, int f0,
                                               int k0, int tid) {
    #pragma unroll
    for (int it = 0; it < 2; it++) {
        int idx = tid + 256 * it;
        int r = (idx & 255) >> 1;
        int c = idx & 1;
        uint32_t o = toff(r, c);
        if (idx < 256) {
            size_t aoff = (size_t)(row0 + r) * D_ + k0 + c * 8;
            cp16(stb + OFF_AHI + o, g_xp_hi + aoff);
            cp16(stb + OFF_ALO + o, g_xp_lo + aoff);
        } else {
            int f = f0 + (r >> 5) * 16 + (r & 15);
            bool up = (r >> 4) & 1;
            size_t boff = ((size_t)e * F_ + f) * D_ + k0 + c * 8;
            cp16(stb + OFF_BHI + o, (up ? g_ut_hi : g_gt_hi) + boff);
            cp16(stb + OFF_BLO + o, (up ? g_ut_lo : g_gt_lo) + boff);
        }
    }
}

static __device__ __forceinline__ void g2_load(uint32_t stb, int row0, int e, int n0,
                                               int k0, int tid) {
    #pragma unroll
    for (int it = 0; it < 2; it++) {
        int idx = tid + 256 * it;
        int r = (idx & 255) >> 1;
        int c = idx & 1;
        uint32_t o = toff(r, c);
        if (idx < 256) {
            size_t aoff = (size_t)(row0 + r) * F_ + k0 + c * 8;
            cp16(stb + OFF_AHI + o, g_act_hi + aoff);
            cp16(stb + OFF_ALO + o, g_act_lo + aoff);
        } else {
            size_t boff = ((size_t)e * D_ + n0 + r) * F_ + k0 + c * 8;
            cp16(stb + OFF_BHI + o, g_dt_hi + boff);
            cp16(stb + OFF_BLO + o, g_dt_lo + boff);
        }
    }
}

static __device__ __forceinline__ void stage_mma(uint32_t stb,
                                                 const uint32_t aOff[4],
                                                 const uint32_t bOff[2],
                                                 float acc[4][4][4]) {
    uint32_t ah[4][4], al[4][4], bh[2][4], bl[2][4];
    #pragma unroll
    for (int i = 0; i < 4; i++) {
        ldsm4(ah[i], stb + OFF_AHI + aOff[i]);
        ldsm4(al[i], stb + OFF_ALO + aOff[i]);
    }
    #pragma unroll
    for (int g = 0; g < 2; g++) {
        ldsm4(bh[g], stb + OFF_BHI + bOff[g]);
        ldsm4(bl[g], stb + OFF_BLO + bOff[g]);
    }
    #pragma unroll
    for (int i = 0; i < 4; i++)
        #pragma unroll
        for (int j = 0; j < 4; j++) {
            const uint32_t* bhj = &bh[j >> 1][(j & 1) * 2];
            const uint32_t* blj = &bl[j >> 1][(j & 1) * 2];
            mma_bf16(acc[i][j], ah[i], bhj);
            mma_bf16(acc[i][j], ah[i], blj);
            mma_bf16(acc[i][j], al[i], bhj);
        }
}

static __device__ __forceinline__ void frag_offs(int wm, int wn, int lane,
                                                 uint32_t aOff[4], uint32_t bOff[2]) {
    #pragma unroll
    for (int i = 0; i < 4; i++)
        aOff[i] = toff(wm * 64 + 16 * i + (lane & 15), lane >> 4);
    #pragma unroll
    for (int g = 0; g < 2; g++)
        bOff[g] = toff(wn * 32 + 16 * g + (lane & 7) + ((lane >> 4) << 3), (lane >> 3) & 1);
}

// ---------------- GEMM1 (mma path) ----------------
__global__ __launch_bounds__(256)
void gemm1_mma() {
    int row0 = blockIdx.y * 128;
    if (row0 >= g_pad_off[E_]) return;
    int e = 0;
    while (e < E_ - 1 && g_pad_off[e + 1] <= row0) e++;
    int f0  = blockIdx.x * 64;
    int tid = threadIdx.x, wid = tid >> 5, lane = tid & 31;
    int wm = wid >> 2, wn = wid & 3;

    __shared__ __align__(128) char smem_buf[2 * STAGE_B];
    uint32_t sb = smem_u32(smem_buf);
    uint32_t st[2] = { sb, sb + STAGE_B };

    uint32_t aOff[4], bOff[2];
    frag_offs(wm, wn, lane, aOff, bOff);

    float acc[4][4][4];
    #pragma unroll
    for (int i = 0; i < 4; i++)
        #pragma unroll
        for (int j = 0; j < 4; j++)
            #pragma unroll
            for (int q = 0; q < 4; q++) acc[i][j][q] = 0.0f;

    const int KT = D_ / BK;
    g1_load(st[0], row0, e, f0, 0, tid);
    cp_commit();
    #pragma unroll 1
    for (int k = 0; k < KT; k++) {
        if (k + 1 < KT) {
            g1_load(st[(k + 1) & 1], row0, e, f0, (k + 1) * BK, tid);
            cp_commit();
            cp_wait<1>();
        } else {
            cp_wait<0>();
        }
        __syncthreads();
        stage_mma(st[k & 1], aOff, bOff, acc);
        __syncthreads();
    }

    #pragma unroll
    for (int i = 0; i < 4; i++)
        #pragma unroll
        for (int j = 0; j < 2; j++) {
            float* ga = acc[i][j];
            float* ua = acc[i][j + 2];
            int fb = f0 + wn * 16 + 8 * j + 2 * (lane & 3);
            #pragma unroll
            for (int hr = 0; hr < 2; hr++) {
                int m = row0 + wm * 64 + 16 * i + (lane >> 2) + 8 * hr;
                float g0 = ga[2 * hr + 0], g1v = ga[2 * hr + 1];
                float u0 = ua[2 * hr + 0], u1v = ua[2 * hr + 1];
                float a0 = (g0 / (1.0f + __expf(-g0))) * u0;
                float a1 = (g1v / (1.0f + __expf(-g1v))) * u1v;
                __nv_bfloat16 h0 = __float2bfloat16(a0);
                __nv_bfloat16 h1 = __float2bfloat16(a1);
                __nv_bfloat16 l0 = __float2bfloat16(a0 - __bfloat162float(h0));
                __nv_bfloat16 l1 = __float2bfloat16(a1 - __bfloat162float(h1));
                size_t off = (size_t)m * F_ + fb;
                *(__nv_bfloat162*)(g_act_hi + off) = __halves2bfloat162(h0, h1);
                *(__nv_bfloat162*)(g_act_lo + off) = __halves2bfloat162(l0, l1);
            }
        }
}

// ---------------- probes ----------------
__global__ void probeA_kernel() {
    int i = blockIdx.x * 256 + threadIdx.x;
    if (i >= PROBE_ACT) return;
    const uint16_t* p = (const uint16_t*)g_act_hi;
    if (p[i] != 0) g_flagA = 1;
}
__global__ void probeB_kernel() {
    int i = blockIdx.x * 256 + threadIdx.x;
    if (i >= PROBE_Y2) return;
    const uint32_t* p = (const uint32_t*)g_y2;
    if (p[i] != 0) g_flagB = 1;
}

// ---------------- SIMT fallbacks (R1-proven math) ----------------
#define SBM 64
#define SBN 64
#define SBK 16

__global__ __launch_bounds__(256)
void gemm1_simt(const float* __restrict__ x,
                const float* __restrict__ gate_w,
                const float* __restrict__ up_w) {
    if (g_flagA) return;                 // mma path produced data; skip
    int row0 = blockIdx.y * SBM;
    if (row0 >= g_pad_off[E_]) return;
    int e = 0;
    while (e < E_ - 1 && g_pad_off[e + 1] <= row0) e++;
    const float* G = gate_w + (size_t)e * D_ * F_;
    const float* U = up_w   + (size_t)e * D_ * F_;
    int n0 = blockIdx.x * SBN;

    __shared__ float As[SBK][SBM + 4];
    __shared__ float Bg[SBK][SBN];
    __shared__ float Bu[SBK][SBN];

    int tid   = threadIdx.x;
    int a_row = tid >> 2;
    int a_k   = (tid & 3) * 4;
    int tok   = g_perm_token[row0 + a_row];
    bool valid = (tok >= 0);
    const float* xrow = x + (size_t)(valid ? tok : 0) * D_;

    int b_k = tid >> 4;
    int b_n = (tid & 15) * 4;
    int ty = tid >> 4, tx = tid & 15;

    float ag[4][4] = {}, au[4][4] = {};

    for (int k0 = 0; k0 < D_; k0 += SBK) {
        float4 av = valid ? *(const float4*)(xrow + k0 + a_k)
                          : make_float4(0.f, 0.f, 0.f, 0.f);
        As[a_k + 0][a_row] = av.x;  As[a_k + 1][a_row] = av.y;
        As[a_k + 2][a_row] = av.z;  As[a_k + 3][a_row] = av.w;
        *(float4*)&Bg[b_k][b_n] = *(const float4*)(G + (size_t)(k0 + b_k) * F_ + n0 + b_n);
        *(float4*)&Bu[b_k][b_n] = *(const float4*)(U + (size_t)(k0 + b_k) * F_ + n0 + b_n);
        __syncthreads();
        #pragma unroll
        for (int kk = 0; kk < SBK; kk++) {
            float4 a4 = *(const float4*)&As[kk][ty * 4];
            float4 g4 = *(const float4*)&Bg[kk][tx * 4];
            float4 u4 = *(const float4*)&Bu[kk][tx * 4];
            float am[4] = {a4.x, a4.y, a4.z, a4.w};
            float gm[4] = {g4.x, g4.y, g4.z, g4.w};
            float um[4] = {u4.x, u4.y, u4.z, u4.w};
            #pragma unroll
            for (int i = 0; i < 4; i++)
                #pragma unroll
                for (int j = 0; j < 4; j++) {
                    ag[i][j] += am[i] * gm[j];
                    au[i][j] += am[i] * um[j];
                }
        }
        __syncthreads();
    }

    #pragma unroll
    for (int i = 0; i < 4; i++) {
        int r = row0 + ty * 4 + i;
        size_t base = (size_t)r * F_ + n0 + tx * 4;
        #pragma unroll
        for (int j = 0; j < 4; j++) {
            float g = ag[i][j], u = au[i][j];
            float a = (g / (1.0f + __expf(-g))) * u;
            __nv_bfloat16 h = __float2bfloat16(a);
            g_act_hi[base + j] = h;
            g_act_lo[base + j] = __float2bfloat16(a - __bfloat162float(h));
        }
    }
}

__global__ __launch_bounds__(256)
void gemm2_simt(const float* __restrict__ down_w) {
    if (g_flagB) return;
    int row0 = blockIdx.y * SBM;
    if (row0 >= g_pad_off[E_]) return;
    int e = 0;
    while (e < E_ - 1 && g_pad_off[e + 1] <= row0) e++;
    const float* Wd = down_w + (size_t)e * F_ * D_;
    int n0 = blockIdx.x * SBN;

    __shared__ float As[SBK][SBM + 4];
    __shared__ float Bs[SBK][SBN];

    int tid   = threadIdx.x;
    int a_row = tid >> 2;
    int a_k   = (tid & 3) * 4;
    size_t abase = (size_t)(row0 + a_row) * F_;

    int b_k = tid >> 4;
    int b_n = (tid & 15) * 4;
    int ty = tid >> 4, tx = tid & 15;

    float acc[4][4] = {};

    for (int k0 = 0; k0 < F_; k0 += SBK) {
        // A = act_hi + act_lo (fp32 reconstruction)
        #pragma unroll
        for (int q = 0; q < 4; q++) {
            size_t off = abase + k0 + a_k + q;
            As[a_k + q][a_row] = __bfloat162float(g_act_hi[off]) + __bfloat162float(g_act_lo[off]);
        }
        *(float4*)&Bs[b_k][b_n] = *(const float4*)(Wd + (size_t)(k0 + b_k) * D_ + n0 + b_n);
        __syncthreads();
        #pragma unroll
        for (int kk = 0; kk < SBK; kk++) {
            float4 a4 = *(const float4*)&As[kk][ty * 4];
            float4 b4 = *(const float4*)&Bs[kk][tx * 4];
            float am[4] = {a4.x, a4.y, a4.z, a4.w};
            float bm[4] = {b4.x, b4.y, b4.z, b4.w};
            #pragma unroll
            for (int i = 0; i < 4; i++)
                #pragma unroll
                for (int j = 0; j < 4; j++)
                    acc[i][j] += am[i] * bm[j];
        }
        __syncthreads();
    }

    #pragma unroll
    for (int i = 0; i < 4; i++) {
        int r = row0 + ty * 4 + i;
        float w = g_perm_w[r];
        float* yrow = g_y2 + (size_t)r * D_ + n0 + tx * 4;
        #pragma unroll
        for (int j = 0; j < 4; j++)
            yrow[j] = acc[i][j] * w;
    }
}

// ---------------- GEMM2 (mma path) ----------------
__global__ __launch_bounds__(256)
void gemm2_mma() {
    int row0 = blockIdx.y * 128;
    if (row0 >= g_pad_off[E_]) return;
    int e = 0;
    while (e < E_ - 1 && g_pad_off[e + 1] <= row0) e++;
    int n0  = blockIdx.x * 128;
    int tid = threadIdx.x, wid = tid >> 5, lane = tid & 31;
    int wm = wid >> 2, wn = wid & 3;

    __shared__ __align__(128) char smem_buf[2 * STAGE_B];
    uint32_t sb = smem_u32(smem_buf);
    uint32_t st[2] = { sb, sb + STAGE_B };

    uint32_t aOff[4], bOff[2];
    frag_offs(wm, wn, lane, aOff, bOff);

    float acc[4][4][4];
    #pragma unroll
    for (int i = 0; i < 4; i++)
        #pragma unroll
        for (int j = 0; j < 4; j++)
            #pragma unroll
            for (int q = 0; q < 4; q++) acc[i][j][q] = 0.0f;

    const int KT = F_ / BK;
    g2_load(st[0], row0, e, n0, 0, tid);
    cp_commit();
    #pragma unroll 1
    for (int k = 0; k < KT; k++) {
        if (k + 1 < KT) {
            g2_load(st[(k + 1) & 1], row0, e, n0, (k + 1) * BK, tid);
            cp_commit();
            cp_wait<1>();
        } else {
            cp_wait<0>();
        }
        __syncthreads();
        stage_mma(st[k & 1], aOff, bOff, acc);
        __syncthreads();
    }

    #pragma unroll
    for (int i = 0; i < 4; i++) {
        float wr[2];
        #pragma unroll
        for (int hr = 0; hr < 2; hr++)
            wr[hr] = g_perm_w[row0 + wm * 64 + 16 * i + (lane >> 2) + 8 * hr];
        #pragma unroll
        for (int j = 0; j < 4; j++) {
            int n = n0 + wn * 32 + 16 * (j >> 1) + 8 * (j & 1) + 2 * (lane & 3);
            #pragma unroll
            for (int hr = 0; hr < 2; hr++) {
                int m = row0 + wm * 64 + 16 * i + (lane >> 2) + 8 * hr;
                float2 v;
                v.x = acc[i][j][2 * hr + 0] * wr[hr];
                v.y = acc[i][j][2 * hr + 1] * wr[hr];
                *(float2*)(g_y2 + (size_t)m * D_ + n) = v;
            }
        }
    }
}

// ---------------- combine ----------------
__global__ void combine_kernel(float* __restrict__ out) {
    int i = blockIdx.x * 256 + threadIdx.x;
    if (i >= OUT_ELEMS) return;
    int t = i >> 10, d = i & 1023;
    int s0 = g_tok_slot[t * 2 + 0];
    int s1 = g_tok_slot[t * 2 + 1];
    out[i] = g_y2[(size_t)s0 * D_ + d] + g_y2[(size_t)s1 * D_ + d];
}

// ---------------- launch ----------------
extern "C" void kernel_launch(void* const* d_in, const int* in_sizes, int n_in,
                              void* d_out, int out_size) {
    const float* x      = (const float*)d_in[0];
    const float* rw     = (const float*)d_in[1];
    const float* gate_w = (const float*)d_in[2];
    const float* up_w   = (const float*)d_in[3];
    const float* down_w = (const float*)d_in[4];
    float* out = (float*)d_out;

    init_kernel<<<(PROBE_ACT + 255) / 256, 256>>>();
    router_kernel<<<NTOK, 256>>>(x, rw);
    scan_kernel<<<1, 1>>>();
    fill_kernel<<<(NSLOT + 255) / 256, 256>>>();
    xgather_kernel<<<SLOT_PAD, 256>>>(x);

    {
        dim3 blk(32, 8);
        dim3 g_gu(F_ / 32, D_ / 32, E_);
        tconv_kernel<<<g_gu, blk>>>(gate_w, g_gt_hi, g_gt_lo, D_, F_);
        tconv_kernel<<<g_gu, blk>>>(up_w,   g_ut_hi, g_ut_lo, D_, F_);
        dim3 g_d(D_ / 32, F_ / 32, E_);
        tconv_kernel<<<g_d, blk>>>(down_w,  g_dt_hi, g_dt_lo, F_, D_);
    }

    // GEMM1: mma attempt, probe, SIMT fallback
    dim3 g1m(F_ / 64, SLOT_PAD / 128);
    gemm1_mma<<<g1m, 256>>>();
    probeA_kernel<<<(PROBE_ACT + 255) / 256, 256>>>();
    dim3 g1s(F_ / SBN, SLOT_PAD / SBM);
    gemm1_simt<<<g1s, 256>>>(x, gate_w, up_w);

    // GEMM2: mma attempt, probe, SIMT fallback
    dim3 g2m(D_ / 128, SLOT_PAD / 128);
    gemm2_mma<<<g2m, 256>>>();
    probeB_kernel<<<(PROBE_Y2 + 255) / 256, 256>>>();
    dim3 g2s(D_ / SBN, SLOT_PAD / SBM);
    gemm2_simt<<<g2s, 256>>>(down_w);

    combine_kernel<<<(OUT_ELEMS + 255) / 256, 256>>>(out);
}

// round 6
// speedup vs baseline: 1.1411x; 1.1411x over previous
#include <cuda_runtime.h>
#include <math.h>
#include <stdint.h>

// ---------------- problem constants ----------------
#define E_        8
#define NTOK      8192
#define D_        1024
#define F_        2816
#define NSLOT     (NTOK * 2)
#define SLOT_PAD  (NSLOT + E_ * 64)    // 16896, expert ranges 64-aligned
#define OUT_ELEMS (NTOK * D_)

#define BKK 16                          // K per smem block

typedef unsigned long long u64;

// ---------------- static device scratch ----------------
__device__ __align__(128) float g_act[(size_t)SLOT_PAD * F_];   // SwiGLU activations
__device__ __align__(128) float g_y2[(size_t)SLOT_PAD * D_];    // weighted expert outputs

__device__ int   g_perm_token[SLOT_PAD];
__device__ float g_perm_w[SLOT_PAD];
__device__ int   g_tok_slot[NSLOT];
__device__ int   g_counts[E_];
__device__ int   g_cursor[E_];
__device__ int   g_pad_off[E_ + 1];
__device__ int   g_topk_idx[NSLOT];
__device__ float g_topk_w[NSLOT];

// ---------------- f32x2 helpers ----------------
static __device__ __forceinline__ u64 pack2(float lo, float hi) {
    u64 r;
    asm("mov.b64 %0, {%1, %2};" : "=l"(r) : "f"(lo), "f"(hi));
    return r;
}
static __device__ __forceinline__ void fma2(u64& d, u64 a, u64 b) {
    asm("fma.rn.f32x2 %0, %1, %2, %0;" : "+l"(d) : "l"(a), "l"(b));
}
static __device__ __forceinline__ float2 unpack2(u64 v) {
    float2 f;
    asm("mov.b64 {%0, %1}, %2;" : "=f"(f.x), "=f"(f.y) : "l"(v));
    return f;
}

// ---------------- pre-pass kernels (R1-proven) ----------------
__global__ void init_kernel() {
    int i = blockIdx.x * 256 + threadIdx.x;
    if (i < SLOT_PAD) { g_perm_token[i] = -1; g_perm_w[i] = 0.0f; }
    if (i < E_) g_counts[i] = 0;
}

__global__ void router_kernel(const float* __restrict__ x, const float* __restrict__ rw) {
    int t = blockIdx.x;
    const float* xr = x + (size_t)t * D_;
    int lane = threadIdx.x & 31;
    int w    = threadIdx.x >> 5;

    double s = 0.0;
    for (int d = lane; d < D_; d += 32)
        s += (double)xr[d] * (double)rw[d * E_ + w];
    #pragma unroll
    for (int o = 16; o > 0; o >>= 1)
        s += __shfl_down_sync(0xffffffffu, s, o);

    __shared__ double sc[E_];
    if (lane == 0) sc[w] = s;
    __syncthreads();

    if (threadIdx.x == 0) {
        double m = sc[0];
        #pragma unroll
        for (int e = 1; e < E_; e++) m = fmax(m, sc[e]);
        double p[E_], sum = 0.0;
        #pragma unroll
        for (int e = 0; e < E_; e++) { p[e] = exp(sc[e] - m); sum += p[e]; }
        #pragma unroll
        for (int e = 0; e < E_; e++) p[e] /= sum;
        int i0 = 0;
        #pragma unroll
        for (int e = 1; e < E_; e++) if (p[e] > p[i0]) i0 = e;
        int i1 = (i0 == 0) ? 1 : 0;
        #pragma unroll
        for (int e = 0; e < E_; e++) { if (e == i0) continue; if (p[e] > p[i1]) i1 = e; }
        float p0 = (float)p[i0], p1 = (float)p[i1];
        float inv = 1.0f / (p0 + p1);
        g_topk_idx[t * 2 + 0] = i0;  g_topk_idx[t * 2 + 1] = i1;
        g_topk_w[t * 2 + 0] = p0 * inv;  g_topk_w[t * 2 + 1] = p1 * inv;
        atomicAdd(&g_counts[i0], 1);
        atomicAdd(&g_counts[i1], 1);
    }
}

__global__ void scan_kernel() {
    int off = 0;
    #pragma unroll
    for (int e = 0; e < E_; e++) {
        g_pad_off[e] = off;  g_cursor[e] = off;
        off += (g_counts[e] + 63) & ~63;
    }
    g_pad_off[E_] = off;
}

__global__ void fill_kernel() {
    int idx = blockIdx.x * blockDim.x + threadIdx.x;
    if (idx >= NSLOT) return;
    int e    = g_topk_idx[idx];
    int slot = atomicAdd(&g_cursor[e], 1);
    g_perm_token[slot] = idx >> 1;
    g_perm_w[slot]     = g_topk_w[idx];
    g_tok_slot[idx]    = slot;
}

// ---------------- GEMM1: act = silu(x@G) * (x@U) ----------------
// CTA: 64 rows x 128 f-cols. 256 threads: ty=tid>>4 (m, 4 rows each),
// tx=tid&15 (f, 8 cols each). f32x2 inner.
__global__ __launch_bounds__(256)
void gemm1_kernel(const float* __restrict__ x,
                  const float* __restrict__ gate_w,
                  const float* __restrict__ up_w) {
    int row0 = blockIdx.y * 64;
    if (row0 >= g_pad_off[E_]) return;
    int e = 0;
    while (e < E_ - 1 && g_pad_off[e + 1] <= row0) e++;
    const float* G = gate_w + (size_t)e * D_ * F_;
    const float* U = up_w   + (size_t)e * D_ * F_;
    int f0 = blockIdx.x * 128;

    __shared__ float As[BKK][68];
    __shared__ float Bg[BKK][128];
    __shared__ float Bu[BKK][128];

    int tid   = threadIdx.x;
    int a_row = tid >> 2;              // 0..63
    int a_k   = (tid & 3) * 4;         // 0,4,8,12
    int tok   = g_perm_token[row0 + a_row];
    bool valid = (tok >= 0);
    const float* xrow = x + (size_t)(valid ? tok : 0) * D_;

    int b_k = tid >> 4;                // 0..15
    int b_f = (tid & 15) * 8;          // 0..120

    int ty = tid >> 4;                 // m group
    int tx = tid & 15;                 // f group

    u64 ag[4][4], au[4][4];
    #pragma unroll
    for (int i = 0; i < 4; i++)
        #pragma unroll
        for (int j = 0; j < 4; j++) { ag[i][j] = 0ull; au[i][j] = 0ull; }

    for (int k0 = 0; k0 < D_; k0 += BKK) {
        float4 av = valid ? *(const float4*)(xrow + k0 + a_k)
                          : make_float4(0.f, 0.f, 0.f, 0.f);
        As[a_k + 0][a_row] = av.x;
        As[a_k + 1][a_row] = av.y;
        As[a_k + 2][a_row] = av.z;
        As[a_k + 3][a_row] = av.w;
        const float* gp = G + (size_t)(k0 + b_k) * F_ + f0 + b_f;
        const float* up = U + (size_t)(k0 + b_k) * F_ + f0 + b_f;
        *(float4*)&Bg[b_k][b_f]     = *(const float4*)(gp);
        *(float4*)&Bg[b_k][b_f + 4] = *(const float4*)(gp + 4);
        *(float4*)&Bu[b_k][b_f]     = *(const float4*)(up);
        *(float4*)&Bu[b_k][b_f + 4] = *(const float4*)(up + 4);
        __syncthreads();

        #pragma unroll
        for (int kk = 0; kk < BKK; kk++) {
            float4 a4 = *(const float4*)&As[kk][ty * 4];
            u64 ad[4];
            ad[0] = pack2(a4.x, a4.x);
            ad[1] = pack2(a4.y, a4.y);
            ad[2] = pack2(a4.z, a4.z);
            ad[3] = pack2(a4.w, a4.w);
            ulonglong2 g01 = *(const ulonglong2*)&Bg[kk][tx * 8];
            ulonglong2 g23 = *(const ulonglong2*)&Bg[kk][tx * 8 + 4];
            ulonglong2 u01 = *(const ulonglong2*)&Bu[kk][tx * 8];
            ulonglong2 u23 = *(const ulonglong2*)&Bu[kk][tx * 8 + 4];
            u64 gb[4] = { g01.x, g01.y, g23.x, g23.y };
            u64 ub[4] = { u01.x, u01.y, u23.x, u23.y };
            #pragma unroll
            for (int i = 0; i < 4; i++)
                #pragma unroll
                for (int j = 0; j < 4; j++) {
                    fma2(ag[i][j], ad[i], gb[j]);
                    fma2(au[i][j], ad[i], ub[j]);
                }
        }
        __syncthreads();
    }

    // epilogue: SwiGLU, write fp32 act
    #pragma unroll
    for (int i = 0; i < 4; i++) {
        int m = row0 + ty * 4 + i;
        float* arow = g_act + (size_t)m * F_ + f0 + tx * 8;
        #pragma unroll
        for (int j = 0; j < 4; j++) {
            float2 g = unpack2(ag[i][j]);
            float2 u = unpack2(au[i][j]);
            float2 o;
            o.x = (g.x / (1.0f + __expf(-g.x))) * u.x;
            o.y = (g.y / (1.0f + __expf(-g.y))) * u.y;
            *(float2*)(arow + 2 * j) = o;
        }
    }
}

// ---------------- GEMM2: y2 = w * (act @ Wdown) ----------------
// CTA: 64 rows x 128 d-cols, same thread layout.
__global__ __launch_bounds__(256)
void gemm2_kernel(const float* __restrict__ down_w) {
    int row0 = blockIdx.y * 64;
    if (row0 >= g_pad_off[E_]) return;
    int e = 0;
    while (e < E_ - 1 && g_pad_off[e + 1] <= row0) e++;
    const float* Wd = down_w + (size_t)e * F_ * D_;
    int n0 = blockIdx.x * 128;

    __shared__ float As[BKK][68];
    __shared__ float Bs[BKK][128];

    int tid   = threadIdx.x;
    int a_row = tid >> 2;
    int a_k   = (tid & 3) * 4;
    const float* arow_g = g_act + (size_t)(row0 + a_row) * F_;

    int b_k = tid >> 4;
    int b_n = (tid & 15) * 8;
    int ty = tid >> 4;
    int tx = tid & 15;

    u64 acc[4][4];
    #pragma unroll
    for (int i = 0; i < 4; i++)
        #pragma unroll
        for (int j = 0; j < 4; j++) acc[i][j] = 0ull;

    for (int k0 = 0; k0 < F_; k0 += BKK) {
        float4 av = *(const float4*)(arow_g + k0 + a_k);
        As[a_k + 0][a_row] = av.x;
        As[a_k + 1][a_row] = av.y;
        As[a_k + 2][a_row] = av.z;
        As[a_k + 3][a_row] = av.w;
        const float* wp = Wd + (size_t)(k0 + b_k) * D_ + n0 + b_n;
        *(float4*)&Bs[b_k][b_n]     = *(const float4*)(wp);
        *(float4*)&Bs[b_k][b_n + 4] = *(const float4*)(wp + 4);
        __syncthreads();

        #pragma unroll
        for (int kk = 0; kk < BKK; kk++) {
            float4 a4 = *(const float4*)&As[kk][ty * 4];
            u64 ad[4];
            ad[0] = pack2(a4.x, a4.x);
            ad[1] = pack2(a4.y, a4.y);
            ad[2] = pack2(a4.z, a4.z);
            ad[3] = pack2(a4.w, a4.w);
            ulonglong2 b01 = *(const ulonglong2*)&Bs[kk][tx * 8];
            ulonglong2 b23 = *(const ulonglong2*)&Bs[kk][tx * 8 + 4];
            u64 bb[4] = { b01.x, b01.y, b23.x, b23.y };
            #pragma unroll
            for (int i = 0; i < 4; i++)
                #pragma unroll
                for (int j = 0; j < 4; j++)
                    fma2(acc[i][j], ad[i], bb[j]);
        }
        __syncthreads();
    }

    // epilogue: scale by routing weight, write y2 (deterministic)
    #pragma unroll
    for (int i = 0; i < 4; i++) {
        int r = row0 + ty * 4 + i;
        float w = g_perm_w[r];
        float* yrow = g_y2 + (size_t)r * D_ + n0 + tx * 8;
        #pragma unroll
        for (int j = 0; j < 4; j++) {
            float2 v = unpack2(acc[i][j]);
            v.x *= w;  v.y *= w;
            *(float2*)(yrow + 2 * j) = v;
        }
    }
}

// ---------------- combine: out[t] = y2[slot0] + y2[slot1] ----------------
__global__ void combine_kernel(float* __restrict__ out) {
    int i = blockIdx.x * 256 + threadIdx.x;
    if (i >= OUT_ELEMS) return;
    int t = i >> 10, d = i & 1023;
    int s0 = g_tok_slot[t * 2 + 0];
    int s1 = g_tok_slot[t * 2 + 1];
    out[i] = g_y2[(size_t)s0 * D_ + d] + g_y2[(size_t)s1 * D_ + d];
}

// ---------------- launch ----------------
extern "C" void kernel_launch(void* const* d_in, const int* in_sizes, int n_in,
                              void* d_out, int out_size) {
    const float* x      = (const float*)d_in[0];
    const float* rw     = (const float*)d_in[1];
    const float* gate_w = (const float*)d_in[2];
    const float* up_w   = (const float*)d_in[3];
    const float* down_w = (const float*)d_in[4];
    float* out = (float*)d_out;

    init_kernel<<<(SLOT_PAD + 255) / 256, 256>>>();
    router_kernel<<<NTOK, 256>>>(x, rw);
    scan_kernel<<<1, 1>>>();
    fill_kernel<<<(NSLOT + 255) / 256, 256>>>();

    dim3 g1(F_ / 128, SLOT_PAD / 64);   // 22 x 264
    gemm1_kernel<<<g1, 256>>>(x, gate_w, up_w);

    dim3 g2(D_ / 128, SLOT_PAD / 64);   // 8 x 264
    gemm2_kernel<<<g2, 256>>>(down_w);

    combine_kernel<<<(OUT_ELEMS + 255) / 256, 256>>>(out);
}

// round 7
// speedup vs baseline: 1.3287x; 1.1644x over previous
#include <cuda_runtime.h>
#include <cuda_fp16.h>
#include <math.h>
#include <stdint.h>

// ---------------- problem constants ----------------
#define E_        8
#define NTOK      8192
#define D_        1024
#define F_        2816
#define NSLOT     (NTOK * 2)
#define SLOT_PAD  (NSLOT + E_ * 128)   // 17408
#define OUT_ELEMS (NTOK * D_)

// mma tiling: CTA 128 x (64f|128d), K=32 fp16 per stage, 3 stages, 1 barrier/stage
#define BK        32
#define TILE_B    8192                  // 128 rows x 64B
#define STAGE_B   (2 * TILE_B)          // A + B = 16KB
#define NS        3                     // 48KB static total

#define PROBE_ACT (128 * F_)
#define PROBE_Y2  (128 * D_)

// ---------------- static device scratch ----------------
__device__ __align__(128) __half g_xp[(size_t)SLOT_PAD * D_];
__device__ __align__(128) __half g_gt[(size_t)E_ * F_ * D_];   // gate^T (E,F,D)
__device__ __align__(128) __half g_ut[(size_t)E_ * F_ * D_];   // up^T   (E,F,D)
__device__ __align__(128) __half g_dt[(size_t)E_ * D_ * F_];   // down^T (E,D,F)
__device__ __align__(128) __half g_act[(size_t)SLOT_PAD * F_];
__device__ __align__(128) float  g_y2[(size_t)SLOT_PAD * D_];

__device__ int   g_perm_token[SLOT_PAD];
__device__ float g_perm_w[SLOT_PAD];
__device__ int   g_tok_slot[NSLOT];
__device__ int   g_counts[E_];
__device__ int   g_cursor[E_];
__device__ int   g_pad_off[E_ + 1];
__device__ int   g_topk_idx[NSLOT];
__device__ float g_topk_w[NSLOT];
__device__ int   g_flagA;
__device__ int   g_flagB;

// ---------------- helpers ----------------
static __device__ __forceinline__ uint32_t smem_u32(const void* p) {
    uint32_t a;
    asm("{ .reg .u64 t; cvta.to.shared.u64 t, %1; cvt.u32.u64 %0, t; }" : "=r"(a) : "l"(p));
    return a;
}
static __device__ __forceinline__ void cp16(uint32_t dst, const __half* src) {
    asm volatile("cp.async.cg.shared.global [%0], [%1], 16;"
                 :: "r"(dst), "l"(__cvta_generic_to_global(src)) : "memory");
}
static __device__ __forceinline__ void cp_commit() {
    asm volatile("cp.async.commit_group;" ::: "memory");
}
template <int N>
static __device__ __forceinline__ void cp_wait() {
    asm volatile("cp.async.wait_group %0;" :: "n"(N) : "memory");
}
static __device__ __forceinline__ void ldsm4(uint32_t* r, uint32_t addr) {
    asm volatile("ldmatrix.sync.aligned.m8n8.x4.shared.b16 {%0,%1,%2,%3}, [%4];"
                 : "=r"(r[0]), "=r"(r[1]), "=r"(r[2]), "=r"(r[3]) : "r"(addr));
}
static __device__ __forceinline__ void mma_f16(float* d, const uint32_t* a, const uint32_t* b) {
    asm volatile("mma.sync.aligned.m16n8k16.row.col.f32.f16.f16.f32 "
                 "{%0,%1,%2,%3}, {%4,%5,%6,%7}, {%8,%9}, {%0,%1,%2,%3};"
                 : "+f"(d[0]), "+f"(d[1]), "+f"(d[2]), "+f"(d[3])
                 : "r"(a[0]), "r"(a[1]), "r"(a[2]), "r"(a[3]), "r"(b[0]), "r"(b[1]));
}
// swizzled byte offset in a 128-row x 64B (4 octet) tile; conflict-free ldsm
static __device__ __forceinline__ uint32_t toff(int r, int c) {
    int line = r >> 1;
    int o = ((r & 1) << 2) | c;
    o ^= (line & 7);
    return (uint32_t)(line * 128 + o * 16);
}

// ---------------- init ----------------
__global__ void init_kernel() {
    int i = blockIdx.x * 256 + threadIdx.x;
    if (i < SLOT_PAD) { g_perm_token[i] = -1; g_perm_w[i] = 0.0f; }
    if (i < E_) g_counts[i] = 0;
    if (i == 0) { g_flagA = 0; g_flagB = 0; }
    if (i < PROBE_ACT) g_act[i] = __float2half(0.0f);
    if (i < PROBE_Y2)  g_y2[i] = 0.0f;
}

// ---------------- router / scan / fill ----------------
__global__ void router_kernel(const float* __restrict__ x, const float* __restrict__ rw) {
    int t = blockIdx.x;
    const float* xr = x + (size_t)t * D_;
    int lane = threadIdx.x & 31;
    int w    = threadIdx.x >> 5;

    double s = 0.0;
    for (int d = lane; d < D_; d += 32)
        s += (double)xr[d] * (double)rw[d * E_ + w];
    #pragma unroll
    for (int o = 16; o > 0; o >>= 1)
        s += __shfl_down_sync(0xffffffffu, s, o);

    __shared__ double sc[E_];
    if (lane == 0) sc[w] = s;
    __syncthreads();

    if (threadIdx.x == 0) {
        double m = sc[0];
        #pragma unroll
        for (int e = 1; e < E_; e++) m = fmax(m, sc[e]);
        double p[E_], sum = 0.0;
        #pragma unroll
        for (int e = 0; e < E_; e++) { p[e] = exp(sc[e] - m); sum += p[e]; }
        #pragma unroll
        for (int e = 0; e < E_; e++) p[e] /= sum;
        int i0 = 0;
        #pragma unroll
        for (int e = 1; e < E_; e++) if (p[e] > p[i0]) i0 = e;
        int i1 = (i0 == 0) ? 1 : 0;
        #pragma unroll
        for (int e = 0; e < E_; e++) { if (e == i0) continue; if (p[e] > p[i1]) i1 = e; }
        float p0 = (float)p[i0], p1 = (float)p[i1];
        float inv = 1.0f / (p0 + p1);
        g_topk_idx[t * 2 + 0] = i0;  g_topk_idx[t * 2 + 1] = i1;
        g_topk_w[t * 2 + 0] = p0 * inv;  g_topk_w[t * 2 + 1] = p1 * inv;
        atomicAdd(&g_counts[i0], 1);
        atomicAdd(&g_counts[i1], 1);
    }
}

__global__ void scan_kernel() {
    int off = 0;
    #pragma unroll
    for (int e = 0; e < E_; e++) {
        g_pad_off[e] = off;  g_cursor[e] = off;
        off += (g_counts[e] + 127) & ~127;
    }
    g_pad_off[E_] = off;
}

__global__ void fill_kernel() {
    int idx = blockIdx.x * blockDim.x + threadIdx.x;
    if (idx >= NSLOT) return;
    int e    = g_topk_idx[idx];
    int slot = atomicAdd(&g_cursor[e], 1);
    g_perm_token[slot] = idx >> 1;
    g_perm_w[slot]     = g_topk_w[idx];
    g_tok_slot[idx]    = slot;
}

__global__ void xgather_kernel(const float* __restrict__ x) {
    int slot = blockIdx.x;
    int tok  = g_perm_token[slot];
    size_t base = (size_t)slot * D_;
    for (int d = threadIdx.x; d < D_; d += blockDim.x) {
        float v = (tok >= 0) ? x[(size_t)tok * D_ + d] : 0.0f;
        g_xp[base + d] = __float2half(v);
    }
}

// per-expert transpose R x C -> C x R, fp16
__global__ void tconv_kernel(const float* __restrict__ in,
                             __half* __restrict__ oh, int R, int C) {
    __shared__ float t[32][33];
    int e  = blockIdx.z;
    int c0 = blockIdx.x * 32, r0 = blockIdx.y * 32;
    const float* src = in + (size_t)e * R * C;
    #pragma unroll
    for (int i = 0; i < 4; i++) {
        int r = r0 + threadIdx.y + i * 8;
        t[threadIdx.y + i * 8][threadIdx.x] = src[(size_t)r * C + c0 + threadIdx.x];
    }
    __syncthreads();
    #pragma unroll
    for (int i = 0; i < 4; i++) {
        int c = c0 + threadIdx.y + i * 8;
        oh[(size_t)e * R * C + (size_t)c * R + r0 + threadIdx.x] =
            __float2half(t[threadIdx.x][threadIdx.y + i * 8]);
    }
}

// ---------------- mma stage loaders (1024 x 16B chunks, 4 per thread) ------
static __device__ __forceinline__ void g1_load(uint32_t stb, int row0, int e, int f0,
                                               int k0, int tid) {
    #pragma unroll
    for (int it = 0; it < 4; it++) {
        int idx = tid + 256 * it;           // 0..1023
        int r = (idx & 511) >> 2;           // 0..127
        int c = idx & 3;                    // octet
        uint32_t o = toff(r, c);
        if (idx < 512) {
            cp16(stb + o, g_xp + (size_t)(row0 + r) * D_ + k0 + c * 8);
        } else {
            int f = f0 + (r >> 5) * 16 + (r & 15);
            const __half* src = ((r >> 4) & 1) ? g_ut : g_gt;
            cp16(stb + TILE_B + o, src + ((size_t)e * F_ + f) * D_ + k0 + c * 8);
        }
    }
}

static __device__ __forceinline__ void g2_load(uint32_t stb, int row0, int e, int n0,
                                               int k0, int tid) {
    #pragma unroll
    for (int it = 0; it < 4; it++) {
        int idx = tid + 256 * it;
        int r = (idx & 511) >> 2;
        int c = idx & 3;
        uint32_t o = toff(r, c);
        if (idx < 512) {
            cp16(stb + o, g_act + (size_t)(row0 + r) * F_ + k0 + c * 8);
        } else {
            cp16(stb + TILE_B + o, g_dt + ((size_t)e * D_ + n0 + r) * F_ + k0 + c * 8);
        }
    }
}

// ---------------- per-stage compute (K=32: two K16 halves) ----------------
static __device__ __forceinline__ void stage_mma(uint32_t stb, int wm, int wn, int lane,
                                                 float acc[4][4][4]) {
    #pragma unroll
    for (int h = 0; h < 2; h++) {
        uint32_t a[4][4], b[2][4];
        #pragma unroll
        for (int i = 0; i < 4; i++)
            ldsm4(a[i], stb + toff(wm * 64 + 16 * i + (lane & 15), 2 * h + (lane >> 4)));
        #pragma unroll
        for (int g = 0; g < 2; g++)
            ldsm4(b[g], stb + TILE_B +
                  toff(wn * 32 + 16 * g + (lane & 7) + ((lane >> 4) << 3),
                       2 * h + ((lane >> 3) & 1)));
        #pragma unroll
        for (int i = 0; i < 4; i++)
            #pragma unroll
            for (int j = 0; j < 4; j++)
                mma_f16(acc[i][j], a[i], &b[j >> 1][(j & 1) * 2]);
    }
}

// ---------------- GEMM1 (mma): act = silu(xp@gate^T) * (xp@up^T) ----------
__global__ __launch_bounds__(256)
void gemm1_mma() {
    int row0 = blockIdx.y * 128;
    if (row0 >= g_pad_off[E_]) return;
    int e = 0;
    while (e < E_ - 1 && g_pad_off[e + 1] <= row0) e++;
    int f0  = blockIdx.x * 64;
    int tid = threadIdx.x, wid = tid >> 5, lane = tid & 31;
    int wm = wid >> 2, wn = wid & 3;

    __shared__ __align__(128) char smem_buf[NS * STAGE_B];
    uint32_t sb = smem_u32(smem_buf);

    float acc[4][4][4];
    #pragma unroll
    for (int i = 0; i < 4; i++)
        #pragma unroll
        for (int j = 0; j < 4; j++)
            #pragma unroll
            for (int q = 0; q < 4; q++) acc[i][j][q] = 0.0f;

    const int KT = D_ / BK;   // 32
    g1_load(sb + 0 * STAGE_B, row0, e, f0, 0, tid);          cp_commit();
    g1_load(sb + 1 * STAGE_B, row0, e, f0, BK, tid);         cp_commit();

    #pragma unroll 1
    for (int k = 0; k < KT; k++) {
        cp_wait<1>();
        __syncthreads();
        if (k + 2 < KT) {
            g1_load(sb + ((k + 2) % NS) * STAGE_B, row0, e, f0, (k + 2) * BK, tid);
            cp_commit();
        } else {
            cp_commit();   // keep group count in lockstep with wait<1>
        }
        stage_mma(sb + (k % NS) * STAGE_B, wm, wn, lane, acc);
    }

    // epilogue: SwiGLU -> fp16 act. acc j in {0,1}=gate, {2,3}=up (same f)
    #pragma unroll
    for (int i = 0; i < 4; i++)
        #pragma unroll
        for (int j = 0; j < 2; j++) {
            float* ga = acc[i][j];
            float* ua = acc[i][j + 2];
            int fb = f0 + wn * 16 + 8 * j + 2 * (lane & 3);
            #pragma unroll
            for (int hr = 0; hr < 2; hr++) {
                int m = row0 + wm * 64 + 16 * i + (lane >> 2) + 8 * hr;
                float g0 = ga[2 * hr + 0], g1v = ga[2 * hr + 1];
                float u0 = ua[2 * hr + 0], u1v = ua[2 * hr + 1];
                float a0 = (g0 / (1.0f + __expf(-g0))) * u0;
                float a1 = (g1v / (1.0f + __expf(-g1v))) * u1v;
                *(__half2*)(g_act + (size_t)m * F_ + fb) =
                    __halves2half2(__float2half(a0), __float2half(a1));
            }
        }
}

// ---------------- GEMM2 (mma): y2 = w * (act @ down^T) ----------------
__global__ __launch_bounds__(256)
void gemm2_mma() {
    int row0 = blockIdx.y * 128;
    if (row0 >= g_pad_off[E_]) return;
    int e = 0;
    while (e < E_ - 1 && g_pad_off[e + 1] <= row0) e++;
    int n0  = blockIdx.x * 128;
    int tid = threadIdx.x, wid = tid >> 5, lane = tid & 31;
    int wm = wid >> 2, wn = wid & 3;

    __shared__ __align__(128) char smem_buf[NS * STAGE_B];
    uint32_t sb = smem_u32(smem_buf);

    float acc[4][4][4];
    #pragma unroll
    for (int i = 0; i < 4; i++)
        #pragma unroll
        for (int j = 0; j < 4; j++)
            #pragma unroll
            for (int q = 0; q < 4; q++) acc[i][j][q] = 0.0f;

    const int KT = F_ / BK;   // 88
    g2_load(sb + 0 * STAGE_B, row0, e, n0, 0, tid);          cp_commit();
    g2_load(sb + 1 * STAGE_B, row0, e, n0, BK, tid);         cp_commit();

    #pragma unroll 1
    for (int k = 0; k < KT; k++) {
        cp_wait<1>();
        __syncthreads();
        if (k + 2 < KT) {
            g2_load(sb + ((k + 2) % NS) * STAGE_B, row0, e, n0, (k + 2) * BK, tid);
            cp_commit();
        } else {
            cp_commit();
        }
        stage_mma(sb + (k % NS) * STAGE_B, wm, wn, lane, acc);
    }

    #pragma unroll
    for (int i = 0; i < 4; i++) {
        float wr[2];
        #pragma unroll
        for (int hr = 0; hr < 2; hr++)
            wr[hr] = g_perm_w[row0 + wm * 64 + 16 * i + (lane >> 2) + 8 * hr];
        #pragma unroll
        for (int j = 0; j < 4; j++) {
            int n = n0 + wn * 32 + 16 * (j >> 1) + 8 * (j & 1) + 2 * (lane & 3);
            #pragma unroll
            for (int hr = 0; hr < 2; hr++) {
                int m = row0 + wm * 64 + 16 * i + (lane >> 2) + 8 * hr;
                float2 v;
                v.x = acc[i][j][2 * hr + 0] * wr[hr];
                v.y = acc[i][j][2 * hr + 1] * wr[hr];
                *(float2*)(g_y2 + (size_t)m * D_ + n) = v;
            }
        }
    }
}

// ---------------- probes ----------------
__global__ void probeA_kernel() {
    int i = blockIdx.x * 256 + threadIdx.x;
    if (i >= PROBE_ACT) return;
    if (((const uint16_t*)g_act)[i] != 0) g_flagA = 1;
}
__global__ void probeB_kernel() {
    int i = blockIdx.x * 256 + threadIdx.x;
    if (i >= PROBE_Y2) return;
    if (((const uint32_t*)g_y2)[i] != 0) g_flagB = 1;
}

// ---------------- SIMT fallbacks (insurance; early-exit when mma worked) ---
#define SBM 64
#define SBN 64
#define SBK 16

__global__ __launch_bounds__(256)
void gemm1_simt(const float* __restrict__ x,
                const float* __restrict__ gate_w,
                const float* __restrict__ up_w) {
    if (g_flagA) return;
    int row0 = blockIdx.y * SBM;
    if (row0 >= g_pad_off[E_]) return;
    int e = 0;
    while (e < E_ - 1 && g_pad_off[e + 1] <= row0) e++;
    const float* G = gate_w + (size_t)e * D_ * F_;
    const float* U = up_w   + (size_t)e * D_ * F_;
    int n0 = blockIdx.x * SBN;

    __shared__ float As[SBK][SBM + 4];
    __shared__ float Bg[SBK][SBN];
    __shared__ float Bu[SBK][SBN];

    int tid   = threadIdx.x;
    int a_row = tid >> 2;
    int a_k   = (tid & 3) * 4;
    int tok   = g_perm_token[row0 + a_row];
    bool valid = (tok >= 0);
    const float* xrow = x + (size_t)(valid ? tok : 0) * D_;

    int b_k = tid >> 4;
    int b_n = (tid & 15) * 4;
    int ty = tid >> 4, tx = tid & 15;

    float ag[4][4] = {}, au[4][4] = {};

    for (int k0 = 0; k0 < D_; k0 += SBK) {
        float4 av = valid ? *(const float4*)(xrow + k0 + a_k)
                          : make_float4(0.f, 0.f, 0.f, 0.f);
        As[a_k + 0][a_row] = av.x;  As[a_k + 1][a_row] = av.y;
        As[a_k + 2][a_row] = av.z;  As[a_k + 3][a_row] = av.w;
        *(float4*)&Bg[b_k][b_n] = *(const float4*)(G + (size_t)(k0 + b_k) * F_ + n0 + b_n);
        *(float4*)&Bu[b_k][b_n] = *(const float4*)(U + (size_t)(k0 + b_k) * F_ + n0 + b_n);
        __syncthreads();
        #pragma unroll
        for (int kk = 0; kk < SBK; kk++) {
            float4 a4 = *(const float4*)&As[kk][ty * 4];
            float4 g4 = *(const float4*)&Bg[kk][tx * 4];
            float4 u4 = *(const float4*)&Bu[kk][tx * 4];
            float am[4] = {a4.x, a4.y, a4.z, a4.w};
            float gm[4] = {g4.x, g4.y, g4.z, g4.w};
            float um[4] = {u4.x, u4.y, u4.z, u4.w};
            #pragma unroll
            for (int i = 0; i < 4; i++)
                #pragma unroll
                for (int j = 0; j < 4; j++) {
                    ag[i][j] += am[i] * gm[j];
                    au[i][j] += am[i] * um[j];
                }
        }
        __syncthreads();
    }

    #pragma unroll
    for (int i = 0; i < 4; i++) {
        int r = row0 + ty * 4 + i;
        size_t base = (size_t)r * F_ + n0 + tx * 4;
        #pragma unroll
        for (int j = 0; j < 4; j++) {
            float g = ag[i][j], u = au[i][j];
            g_act[base + j] = __float2half((g / (1.0f + __expf(-g))) * u);
        }
    }
}

__global__ __launch_bounds__(256)
void gemm2_simt(const float* __restrict__ down_w) {
    if (g_flagB) return;
    int row0 = blockIdx.y * SBM;
    if (row0 >= g_pad_off[E_]) return;
    int e = 0;
    while (e < E_ - 1 && g_pad_off[e + 1] <= row0) e++;
    const float* Wd = down_w + (size_t)e * F_ * D_;
    int n0 = blockIdx.x * SBN;

    __shared__ float As[SBK][SBM + 4];
    __shared__ float Bs[SBK][SBN];

    int tid   = threadIdx.x;
    int a_row = tid >> 2;
    int a_k   = (tid & 3) * 4;
    size_t abase = (size_t)(row0 + a_row) * F_;

    int b_k = tid >> 4;
    int b_n = (tid & 15) * 4;
    int ty = tid >> 4, tx = tid & 15;

    float acc[4][4] = {};

    for (int k0 = 0; k0 < F_; k0 += SBK) {
        #pragma unroll
        for (int q = 0; q < 4; q++)
            As[a_k + q][a_row] = __half2float(g_act[abase + k0 + a_k + q]);
        *(float4*)&Bs[b_k][b_n] = *(const float4*)(Wd + (size_t)(k0 + b_k) * D_ + n0 + b_n);
        __syncthreads();
        #pragma unroll
        for (int kk = 0; kk < SBK; kk++) {
            float4 a4 = *(const float4*)&As[kk][ty * 4];
            float4 b4 = *(const float4*)&Bs[kk][tx * 4];
            float am[4] = {a4.x, a4.y, a4.z, a4.w};
            float bm[4] = {b4.x, b4.y, b4.z, b4.w};
            #pragma unroll
            for (int i = 0; i < 4; i++)
                #pragma unroll
                for (int j = 0; j < 4; j++)
                    acc[i][j] += am[i] * bm[j];
        }
        __syncthreads();
    }

    #pragma unroll
    for (int i = 0; i < 4; i++) {
        int r = row0 + ty * 4 + i;
        float w = g_perm_w[r];
        float* yrow = g_y2 + (size_t)r * D_ + n0 + tx * 4;
        #pragma unroll
        for (int j = 0; j < 4; j++)
            yrow[j] = acc[i][j] * w;
    }
}

// ---------------- combine ----------------
__global__ void combine_kernel(float* __restrict__ out) {
    int i = blockIdx.x * 256 + threadIdx.x;
    if (i >= OUT_ELEMS) return;
    int t = i >> 10, d = i & 1023;
    int s0 = g_tok_slot[t * 2 + 0];
    int s1 = g_tok_slot[t * 2 + 1];
    out[i] = g_y2[(size_t)s0 * D_ + d] + g_y2[(size_t)s1 * D_ + d];
}

// ---------------- launch ----------------
extern "C" void kernel_launch(void* const* d_in, const int* in_sizes, int n_in,
                              void* d_out, int out_size) {
    const float* x      = (const float*)d_in[0];
    const float* rw     = (const float*)d_in[1];
    const float* gate_w = (const float*)d_in[2];
    const float* up_w   = (const float*)d_in[3];
    const float* down_w = (const float*)d_in[4];
    float* out = (float*)d_out;

    init_kernel<<<(PROBE_ACT + 255) / 256, 256>>>();
    router_kernel<<<NTOK, 256>>>(x, rw);
    scan_kernel<<<1, 1>>>();
    fill_kernel<<<(NSLOT + 255) / 256, 256>>>();
    xgather_kernel<<<SLOT_PAD, 256>>>(x);

    {
        dim3 blk(32, 8);
        dim3 g_gu(F_ / 32, D_ / 32, E_);
        tconv_kernel<<<g_gu, blk>>>(gate_w, g_gt, D_, F_);
        tconv_kernel<<<g_gu, blk>>>(up_w,   g_ut, D_, F_);
        dim3 g_d(D_ / 32, F_ / 32, E_);
        tconv_kernel<<<g_d, blk>>>(down_w,  g_dt, F_, D_);
    }

    dim3 g1m(F_ / 64, SLOT_PAD / 128);   // 44 x 136
    gemm1_mma<<<g1m, 256>>>();
    probeA_kernel<<<(PROBE_ACT + 255) / 256, 256>>>();
    dim3 g1s(F_ / SBN, SLOT_PAD / SBM);
    gemm1_simt<<<g1s, 256>>>(x, gate_w, up_w);

    dim3 g2m(D_ / 128, SLOT_PAD / 128);  // 8 x 136
    gemm2_mma<<<g2m, 256>>>();
    probeB_kernel<<<(PROBE_Y2 + 255) / 256, 256>>>();
    dim3 g2s(D_ / SBN, SLOT_PAD / SBM);
    gemm2_simt<<<g2s, 256>>>(down_w);

    combine_kernel<<<(OUT_ELEMS + 255) / 256, 256>>>(out);
}